// round 3
// baseline (speedup 1.0000x reference)
#include <cuda_runtime.h>
#include <cstdint>
#include <cstddef>

#define NN 100000
#define EE 1000000
#define DD 64
#define KK 8
#define LL 3

#define SCAN_TPB 1024
#define SCAN_BLOCKS ((NN + SCAN_TPB - 1) / SCAN_TPB)   // 98
#define NBINS 64

// ---------------- device scratch (statically allocated; no runtime alloc) ----------------
__device__ float g_T[7][(size_t)NN * DD];
__device__ float g_out1[(size_t)NN * DD];
__device__ float g_out2[(size_t)NN * DD];
__device__ float g_deg[NN];
__device__ float g_dinv[NN];
__device__ int   g_cnt[NN];        // in-degree histogram (kept for bin sort)
__device__ int   g_rowstart[NN + 1];
__device__ int   g_cursor[NN];
__device__ int   g_bsum[SCAN_BLOCKS + 32];
__device__ int   g_dbins[NBINS];
__device__ int   g_dcur[NBINS];
__device__ int   g_perm[NN];
__device__ float2 g_adj[EE];       // packed (src_as_float_bits, norm)

// ---------------- normalization + CSR build ----------------
__global__ void deg_hist_kernel(const int* __restrict__ src, const int* __restrict__ dst,
                                const float* __restrict__ w,
                                float* __restrict__ deg, int* __restrict__ cnt) {
    int e = blockIdx.x * blockDim.x + threadIdx.x;
    if (e >= EE) return;
    int s = src[e], d = dst[e];
    float ww = (s == d) ? 0.0f : w[e];
    if (ww != 0.0f) atomicAdd(&deg[s], ww);
    atomicAdd(&cnt[d], 1);
}

__global__ void dinv_kernel(const float* __restrict__ deg, float* __restrict__ dinv) {
    int i = blockIdx.x * blockDim.x + threadIdx.x;
    if (i >= NN) return;
    float d = deg[i];
    dinv[i] = (d > 0.0f) ? rsqrtf(d) : 0.0f;
}

__global__ void scan_block_kernel(const int* __restrict__ cnt, int* __restrict__ rowstart,
                                  int* __restrict__ bsum) {
    __shared__ int s[SCAN_TPB];
    int i = blockIdx.x * SCAN_TPB + threadIdx.x;
    int v = (i < NN) ? cnt[i] : 0;
    s[threadIdx.x] = v;
    __syncthreads();
#pragma unroll
    for (int off = 1; off < SCAN_TPB; off <<= 1) {
        int t = (threadIdx.x >= off) ? s[threadIdx.x - off] : 0;
        __syncthreads();
        s[threadIdx.x] += t;
        __syncthreads();
    }
    if (i < NN) rowstart[i] = s[threadIdx.x] - v;   // exclusive
    if (threadIdx.x == SCAN_TPB - 1) bsum[blockIdx.x] = s[threadIdx.x];
}

__global__ void scan_sums_kernel(int* __restrict__ bsum) {
    __shared__ int s[128];
    int t = threadIdx.x;
    int v = (t < SCAN_BLOCKS) ? bsum[t] : 0;
    s[t] = v;
    __syncthreads();
#pragma unroll
    for (int off = 1; off < 128; off <<= 1) {
        int tt = (t >= off) ? s[t - off] : 0;
        __syncthreads();
        s[t] += tt;
        __syncthreads();
    }
    if (t < SCAN_BLOCKS) bsum[t] = s[t] - v;
}

__global__ void scan_add_kernel(int* __restrict__ rowstart, const int* __restrict__ bsum,
                                int* __restrict__ cursor) {
    int i = blockIdx.x * blockDim.x + threadIdx.x;
    if (i == 0) rowstart[NN] = EE;
    if (i >= NN) return;
    int r = rowstart[i] + bsum[i / SCAN_TPB];
    rowstart[i] = r;
    cursor[i] = r;
}

__global__ void scatter_kernel(const int* __restrict__ src, const int* __restrict__ dst,
                               const float* __restrict__ w, const float* __restrict__ dinv,
                               int* __restrict__ cursor, float2* __restrict__ adj) {
    int e = blockIdx.x * blockDim.x + threadIdx.x;
    if (e >= EE) return;
    int s = src[e], d = dst[e];
    float ww = (s == d) ? 0.0f : w[e];
    float nrm = -dinv[s] * ww * dinv[d];
    int pos = atomicAdd(&cursor[d], 1);
    adj[pos] = make_float2(__int_as_float(s), nrm);
}

// ---------------- degree-sort (counting sort into perm) ----------------
__global__ void bin_hist_kernel(const int* __restrict__ cnt, int* __restrict__ dbins) {
    int i = blockIdx.x * blockDim.x + threadIdx.x;
    if (i >= NN) return;
    int b = min(cnt[i], NBINS - 1);
    atomicAdd(&dbins[b], 1);
}

__global__ void bin_scan_kernel(const int* __restrict__ dbins, int* __restrict__ dcur) {
    __shared__ int s[NBINS];
    int t = threadIdx.x;
    int v = dbins[t];
    s[t] = v;
    __syncthreads();
#pragma unroll
    for (int off = 1; off < NBINS; off <<= 1) {
        int tt = (t >= off) ? s[t - off] : 0;
        __syncthreads();
        s[t] += tt;
        __syncthreads();
    }
    dcur[t] = s[t] - v;   // exclusive
}

__global__ void bin_scatter_kernel(const int* __restrict__ cnt, int* __restrict__ dcur,
                                   int* __restrict__ perm) {
    int i = blockIdx.x * blockDim.x + threadIdx.x;
    if (i >= NN) return;
    int b = min(cnt[i], NBINS - 1);
    int pos = atomicAdd(&dcur[b], 1);
    perm[pos] = i;
}

// ---------------- CSR gather propagation (4 lanes/node, f32x2 FMA) ----------------
// Lane owns float4-columns {lane, lane+4, lane+8, lane+12}.
#define FMA2(a, v, w) asm("fma.rn.f32x2 %0, %1, %2, %0;" : "+l"(a) : "l"(v), "l"(w))

template <bool FIRST>
__global__ __launch_bounds__(256)
void prop4_kernel(const float* __restrict__ h, const float2* __restrict__ adj,
                  const int* __restrict__ rowstart, const int* __restrict__ perm,
                  const float* __restrict__ t0, float* __restrict__ out) {
    unsigned tid = blockIdx.x * blockDim.x + threadIdx.x;
    unsigned g = tid >> 2;
    if (g >= NN) return;
    unsigned lane = tid & 3u;
    int n = perm[g];
    int r0 = rowstart[n];
    int r1 = rowstart[n + 1];

    unsigned long long acc[8];
#pragma unroll
    for (int i = 0; i < 8; i++) acc[i] = 0ull;

    const ulonglong2* hb = reinterpret_cast<const ulonglong2*>(h);

    int e = r0;
#pragma unroll 1
    for (; e + 1 < r1; e += 2) {
        float2 p0 = __ldg(&adj[e]);
        float2 p1 = __ldg(&adj[e + 1]);
        unsigned long long w0, w1;
        asm("mov.b64 %0, {%1, %1};" : "=l"(w0) : "f"(p0.y));
        asm("mov.b64 %0, {%1, %1};" : "=l"(w1) : "f"(p1.y));
        const ulonglong2* h0 = hb + (size_t)__float_as_int(p0.x) * 16 + lane;
        const ulonglong2* h1 = hb + (size_t)__float_as_int(p1.x) * 16 + lane;
        ulonglong2 a0 = h0[0], a1 = h0[4], a2 = h0[8], a3 = h0[12];
        ulonglong2 b0 = h1[0], b1 = h1[4], b2 = h1[8], b3 = h1[12];
        FMA2(acc[0], a0.x, w0); FMA2(acc[1], a0.y, w0);
        FMA2(acc[2], a1.x, w0); FMA2(acc[3], a1.y, w0);
        FMA2(acc[4], a2.x, w0); FMA2(acc[5], a2.y, w0);
        FMA2(acc[6], a3.x, w0); FMA2(acc[7], a3.y, w0);
        FMA2(acc[0], b0.x, w1); FMA2(acc[1], b0.y, w1);
        FMA2(acc[2], b1.x, w1); FMA2(acc[3], b1.y, w1);
        FMA2(acc[4], b2.x, w1); FMA2(acc[5], b2.y, w1);
        FMA2(acc[6], b3.x, w1); FMA2(acc[7], b3.y, w1);
    }
    if (e < r1) {
        float2 p0 = __ldg(&adj[e]);
        unsigned long long w0;
        asm("mov.b64 %0, {%1, %1};" : "=l"(w0) : "f"(p0.y));
        const ulonglong2* h0 = hb + (size_t)__float_as_int(p0.x) * 16 + lane;
        ulonglong2 a0 = h0[0], a1 = h0[4], a2 = h0[8], a3 = h0[12];
        FMA2(acc[0], a0.x, w0); FMA2(acc[1], a0.y, w0);
        FMA2(acc[2], a1.x, w0); FMA2(acc[3], a1.y, w0);
        FMA2(acc[4], a2.x, w0); FMA2(acc[5], a2.y, w0);
        FMA2(acc[6], a3.x, w0); FMA2(acc[7], a3.y, w0);
    }

    // epilogue: unpack and write 4 float4s at column (lane + 4*j)
#pragma unroll
    for (int j = 0; j < 4; j++) {
        float x0, x1, x2, x3;
        asm("mov.b64 {%0, %1}, %2;" : "=f"(x0), "=f"(x1) : "l"(acc[2 * j]));
        asm("mov.b64 {%0, %1}, %2;" : "=f"(x2), "=f"(x3) : "l"(acc[2 * j + 1]));
        size_t idx = (size_t)n * 16 + lane + 4 * j;   // float4 index
        if (FIRST) {
            reinterpret_cast<float4*>(out)[idx] = make_float4(x0, x1, x2, x3);
        } else {
            float4 t = reinterpret_cast<const float4*>(t0)[idx];
            reinterpret_cast<float4*>(out)[idx] =
                make_float4(2.0f * x0 - t.x, 2.0f * x1 - t.y,
                            2.0f * x2 - t.z, 2.0f * x3 - t.w);
        }
    }
}

// ---------------- fused 8-way GEMM + bias + relu ----------------
struct TPtrs { const float* p[KK]; };

__global__ void gemm8_kernel(TPtrs ts, const float* __restrict__ W,
                             const float* __restrict__ bias, float* __restrict__ out) {
    __shared__ float Xs[128][DD];
    __shared__ float Ws[DD][DD];
    int tid = threadIdx.x;
    int row0 = blockIdx.x * 128;
    int tx = tid & 15, ty = tid >> 4;

    float accR[8][4];
#pragma unroll
    for (int i = 0; i < 8; i++)
#pragma unroll
        for (int c = 0; c < 4; c++) accR[i][c] = 0.0f;

    for (int k = 0; k < KK; ++k) {
        const float* X = ts.p[k];
        const float* Wp = W + (size_t)k * DD * DD;
#pragma unroll
        for (int i = 0; i < 4; i++) {
            int f4 = tid + i * 256;
            reinterpret_cast<float4*>(Ws)[f4] = reinterpret_cast<const float4*>(Wp)[f4];
        }
#pragma unroll
        for (int i = 0; i < 8; i++) {
            int f4 = tid + i * 256;
            int r = f4 >> 4, c4 = f4 & 15;
            int gr = row0 + r;
            float4 v = make_float4(0.f, 0.f, 0.f, 0.f);
            if (gr < NN) v = reinterpret_cast<const float4*>(X + (size_t)gr * DD)[c4];
            reinterpret_cast<float4*>(&Xs[r][0])[c4] = v;
        }
        __syncthreads();
#pragma unroll 8
        for (int j = 0; j < DD; j++) {
            float4 b = reinterpret_cast<float4*>(&Ws[j][0])[tx];
            float a[8];
#pragma unroll
            for (int i = 0; i < 8; i++) a[i] = Xs[ty * 8 + i][j];
#pragma unroll
            for (int i = 0; i < 8; i++) {
                accR[i][0] = fmaf(a[i], b.x, accR[i][0]);
                accR[i][1] = fmaf(a[i], b.y, accR[i][1]);
                accR[i][2] = fmaf(a[i], b.z, accR[i][2]);
                accR[i][3] = fmaf(a[i], b.w, accR[i][3]);
            }
        }
        __syncthreads();
    }

    float4 b4 = reinterpret_cast<const float4*>(bias)[tx];
#pragma unroll
    for (int i = 0; i < 8; i++) {
        int gr = row0 + ty * 8 + i;
        if (gr < NN) {
            float4 v;
            v.x = fmaxf(accR[i][0] + b4.x, 0.f);
            v.y = fmaxf(accR[i][1] + b4.y, 0.f);
            v.z = fmaxf(accR[i][2] + b4.z, 0.f);
            v.w = fmaxf(accR[i][3] + b4.w, 0.f);
            reinterpret_cast<float4*>(out + (size_t)gr * DD)[tx] = v;
        }
    }
}

// ---------------- launcher ----------------
extern "C" void kernel_launch(void* const* d_in, const int* in_sizes, int n_in,
                              void* d_out, int out_size) {
    const float* x  = (const float*)d_in[0];
    const int*   ei = (const int*)d_in[1];
    const float* ew = (const float*)d_in[2];
    const float* Wt = (const float*)d_in[3];
    const float* Bs = (const float*)d_in[4];
    const int* src = ei;
    const int* dst = ei + EE;

    float *Tbuf, *out1, *out2, *deg, *dinv;
    int *cnt, *rowstart, *cursor, *bsum, *dbins, *dcur, *perm;
    float2* adj;
    cudaGetSymbolAddress((void**)&Tbuf, g_T);
    cudaGetSymbolAddress((void**)&out1, g_out1);
    cudaGetSymbolAddress((void**)&out2, g_out2);
    cudaGetSymbolAddress((void**)&deg, g_deg);
    cudaGetSymbolAddress((void**)&dinv, g_dinv);
    cudaGetSymbolAddress((void**)&cnt, g_cnt);
    cudaGetSymbolAddress((void**)&rowstart, g_rowstart);
    cudaGetSymbolAddress((void**)&cursor, g_cursor);
    cudaGetSymbolAddress((void**)&bsum, g_bsum);
    cudaGetSymbolAddress((void**)&dbins, g_dbins);
    cudaGetSymbolAddress((void**)&dcur, g_dcur);
    cudaGetSymbolAddress((void**)&perm, g_perm);
    cudaGetSymbolAddress((void**)&adj, g_adj);

    const size_t FB = (size_t)NN * DD;
    float* TB[7];
    for (int i = 0; i < 7; i++) TB[i] = Tbuf + (size_t)i * FB;

    const int T = 256;
    const int edgeBlocks = (EE + T - 1) / T;
    const int nodeBlocks = (NN + T - 1) / T;
    const int propBlocks = (NN * 4 + T - 1) / T;
    const int gemmBlocks = (NN + 127) / 128;

    // --- normalization + CSR + degree sort (stateless each call) ---
    cudaMemsetAsync(deg, 0, NN * sizeof(float));
    cudaMemsetAsync(cnt, 0, NN * sizeof(int));
    cudaMemsetAsync(dbins, 0, NBINS * sizeof(int));
    deg_hist_kernel<<<edgeBlocks, T>>>(src, dst, ew, deg, cnt);
    dinv_kernel<<<nodeBlocks, T>>>(deg, dinv);
    scan_block_kernel<<<SCAN_BLOCKS, SCAN_TPB>>>(cnt, rowstart, bsum);
    scan_sums_kernel<<<1, 128>>>(bsum);
    scan_add_kernel<<<nodeBlocks, T>>>(rowstart, bsum, cursor);
    scatter_kernel<<<edgeBlocks, T>>>(src, dst, ew, dinv, cursor, adj);
    bin_hist_kernel<<<nodeBlocks, T>>>(cnt, dbins);
    bin_scan_kernel<<<1, NBINS>>>(dbins, dcur);
    bin_scatter_kernel<<<nodeBlocks, T>>>(cnt, dcur, perm);

    // --- layers ---
    const float* hin = x;
    float* houts[3] = {out1, out2, (float*)d_out};

    for (int l = 0; l < LL; l++) {
        const float* Wl = Wt + (size_t)l * KK * DD * DD;
        prop4_kernel<true><<<propBlocks, T>>>(hin, adj, rowstart, perm, nullptr, TB[0]);
        for (int k = 2; k < KK; k++) {
            const float* tin = TB[k - 2];
            const float* t0 = (k == 2) ? hin : TB[k - 3];
            prop4_kernel<false><<<propBlocks, T>>>(tin, adj, rowstart, perm, t0, TB[k - 1]);
        }
        TPtrs ts;
        ts.p[0] = hin;
        for (int k = 1; k < KK; k++) ts.p[k] = TB[k - 1];
        gemm8_kernel<<<gemmBlocks, T>>>(ts, Wl, Bs + (size_t)l * DD, houts[l]);
        hin = houts[l];
    }
}

// round 4
// speedup vs baseline: 1.0773x; 1.0773x over previous
#include <cuda_runtime.h>
#include <cstdint>
#include <cstddef>

#define NN 100000
#define EE 1000000
#define DD 64
#define KK 8
#define LL 3

#define SCAN_TPB 1024
#define SCAN_BLOCKS ((NN + SCAN_TPB - 1) / SCAN_TPB)   // 98
#define NBINS 64

// ---------------- device scratch (statically allocated; no runtime alloc) ----------------
__device__ float g_T[7][(size_t)NN * DD];
__device__ float g_out1[(size_t)NN * DD];
__device__ float g_out2[(size_t)NN * DD];
__device__ float g_xp[(size_t)NN * DD];     // x permuted into degree-sorted space
__device__ float g_deg[NN];
__device__ float g_dinv[NN];
__device__ int   g_cnt[NN];                 // in-degree by original node id
__device__ int   g_cntp[NN];                // in-degree by permuted id
__device__ int   g_rowstart[NN + 1];        // CSR rowstart in permuted space
__device__ int   g_cursor[NN];
__device__ int   g_bsum[SCAN_BLOCKS + 32];
__device__ int   g_dbins[NBINS];
__device__ int   g_dcur[NBINS];
__device__ int   g_perm[NN];                // perm[g] = original id
__device__ int   g_rank[NN];                // rank[orig] = g
__device__ float2 g_adj[EE];                // (src_rank_as_float_bits, norm)

// ---------------- normalization ----------------
__global__ void deg_hist_kernel(const int* __restrict__ src, const int* __restrict__ dst,
                                const float* __restrict__ w,
                                float* __restrict__ deg, int* __restrict__ cnt) {
    int e = blockIdx.x * blockDim.x + threadIdx.x;
    if (e >= EE) return;
    int s = src[e], d = dst[e];
    float ww = (s == d) ? 0.0f : w[e];
    if (ww != 0.0f) atomicAdd(&deg[s], ww);
    atomicAdd(&cnt[d], 1);
}

__global__ void dinv_kernel(const float* __restrict__ deg, float* __restrict__ dinv) {
    int i = blockIdx.x * blockDim.x + threadIdx.x;
    if (i >= NN) return;
    float d = deg[i];
    dinv[i] = (d > 0.0f) ? rsqrtf(d) : 0.0f;
}

// ---------------- degree bin sort ----------------
__global__ void bin_hist_kernel(const int* __restrict__ cnt, int* __restrict__ dbins) {
    int i = blockIdx.x * blockDim.x + threadIdx.x;
    if (i >= NN) return;
    atomicAdd(&dbins[min(cnt[i], NBINS - 1)], 1);
}

__global__ void bin_scan_kernel(const int* __restrict__ dbins, int* __restrict__ dcur) {
    __shared__ int s[NBINS];
    int t = threadIdx.x;
    int v = dbins[t];
    s[t] = v;
    __syncthreads();
#pragma unroll
    for (int off = 1; off < NBINS; off <<= 1) {
        int tt = (t >= off) ? s[t - off] : 0;
        __syncthreads();
        s[t] += tt;
        __syncthreads();
    }
    dcur[t] = s[t] - v;
}

__global__ void bin_scatter_kernel(const int* __restrict__ cnt, int* __restrict__ dcur,
                                   int* __restrict__ perm, int* __restrict__ rank) {
    int i = blockIdx.x * blockDim.x + threadIdx.x;
    if (i >= NN) return;
    int pos = atomicAdd(&dcur[min(cnt[i], NBINS - 1)], 1);
    perm[pos] = i;
    rank[i] = pos;
}

__global__ void cntp_kernel(const int* __restrict__ cnt, const int* __restrict__ perm,
                            int* __restrict__ cntp) {
    int g = blockIdx.x * blockDim.x + threadIdx.x;
    if (g >= NN) return;
    cntp[g] = cnt[perm[g]];
}

// x_p[g] = x[perm[g]]  (float4 lanes; coalesced writes)
__global__ void permute_x_kernel(const float* __restrict__ x, const int* __restrict__ perm,
                                 float* __restrict__ xp) {
    unsigned tid = blockIdx.x * blockDim.x + threadIdx.x;
    unsigned g = tid >> 4;
    if (g >= NN) return;
    unsigned lane = tid & 15u;
    int n = perm[g];
    reinterpret_cast<float4*>(xp)[(size_t)g * 16 + lane] =
        reinterpret_cast<const float4*>(x)[(size_t)n * 16 + lane];
}

// ---------------- scan (exclusive) of cntp -> rowstart ----------------
__global__ void scan_block_kernel(const int* __restrict__ cnt, int* __restrict__ rowstart,
                                  int* __restrict__ bsum) {
    __shared__ int s[SCAN_TPB];
    int i = blockIdx.x * SCAN_TPB + threadIdx.x;
    int v = (i < NN) ? cnt[i] : 0;
    s[threadIdx.x] = v;
    __syncthreads();
#pragma unroll
    for (int off = 1; off < SCAN_TPB; off <<= 1) {
        int t = (threadIdx.x >= off) ? s[threadIdx.x - off] : 0;
        __syncthreads();
        s[threadIdx.x] += t;
        __syncthreads();
    }
    if (i < NN) rowstart[i] = s[threadIdx.x] - v;
    if (threadIdx.x == SCAN_TPB - 1) bsum[blockIdx.x] = s[threadIdx.x];
}

__global__ void scan_sums_kernel(int* __restrict__ bsum) {
    __shared__ int s[128];
    int t = threadIdx.x;
    int v = (t < SCAN_BLOCKS) ? bsum[t] : 0;
    s[t] = v;
    __syncthreads();
#pragma unroll
    for (int off = 1; off < 128; off <<= 1) {
        int tt = (t >= off) ? s[t - off] : 0;
        __syncthreads();
        s[t] += tt;
        __syncthreads();
    }
    if (t < SCAN_BLOCKS) bsum[t] = s[t] - v;
}

__global__ void scan_add_kernel(int* __restrict__ rowstart, const int* __restrict__ bsum,
                                int* __restrict__ cursor) {
    int i = blockIdx.x * blockDim.x + threadIdx.x;
    if (i == 0) rowstart[NN] = EE;
    if (i >= NN) return;
    int r = rowstart[i] + bsum[i / SCAN_TPB];
    rowstart[i] = r;
    cursor[i] = r;
}

// Scatter edges into permuted CSR; src stored as rank (permuted id).
__global__ void scatter_kernel(const int* __restrict__ src, const int* __restrict__ dst,
                               const float* __restrict__ w, const float* __restrict__ dinv,
                               const int* __restrict__ rank,
                               int* __restrict__ cursor, float2* __restrict__ adj) {
    int e = blockIdx.x * blockDim.x + threadIdx.x;
    if (e >= EE) return;
    int s = src[e], d = dst[e];
    float ww = (s == d) ? 0.0f : w[e];
    float nrm = -dinv[s] * ww * dinv[d];
    int pos = atomicAdd(&cursor[rank[d]], 1);
    adj[pos] = make_float2(__int_as_float(rank[s]), nrm);
}

// ---------------- CSR gather propagation ----------------
// 16 lanes/node in permuted space: coalesced out/t0, degree-uniform warps.
// Unroll-4 for MLP against L2 latency.
template <bool FIRST>
__global__ __launch_bounds__(256)
void prop16_kernel(const float* __restrict__ h, const float2* __restrict__ adj,
                   const int* __restrict__ rowstart, const float* __restrict__ t0,
                   float* __restrict__ out) {
    unsigned tid = blockIdx.x * blockDim.x + threadIdx.x;
    unsigned n = tid >> 4;
    if (n >= NN) return;
    unsigned lane = tid & 15u;
    int r0 = rowstart[n];
    int r1 = rowstart[n + 1];

    float4 acc = make_float4(0.f, 0.f, 0.f, 0.f);
    const float4* hb = reinterpret_cast<const float4*>(h);

    int e = r0;
#pragma unroll 1
    for (; e + 3 < r1; e += 4) {
        float2 p0 = __ldg(&adj[e]);
        float2 p1 = __ldg(&adj[e + 1]);
        float2 p2 = __ldg(&adj[e + 2]);
        float2 p3 = __ldg(&adj[e + 3]);
        float4 v0 = hb[(size_t)__float_as_int(p0.x) * 16 + lane];
        float4 v1 = hb[(size_t)__float_as_int(p1.x) * 16 + lane];
        float4 v2 = hb[(size_t)__float_as_int(p2.x) * 16 + lane];
        float4 v3 = hb[(size_t)__float_as_int(p3.x) * 16 + lane];
        acc.x = fmaf(p0.y, v0.x, acc.x); acc.y = fmaf(p0.y, v0.y, acc.y);
        acc.z = fmaf(p0.y, v0.z, acc.z); acc.w = fmaf(p0.y, v0.w, acc.w);
        acc.x = fmaf(p1.y, v1.x, acc.x); acc.y = fmaf(p1.y, v1.y, acc.y);
        acc.z = fmaf(p1.y, v1.z, acc.z); acc.w = fmaf(p1.y, v1.w, acc.w);
        acc.x = fmaf(p2.y, v2.x, acc.x); acc.y = fmaf(p2.y, v2.y, acc.y);
        acc.z = fmaf(p2.y, v2.z, acc.z); acc.w = fmaf(p2.y, v2.w, acc.w);
        acc.x = fmaf(p3.y, v3.x, acc.x); acc.y = fmaf(p3.y, v3.y, acc.y);
        acc.z = fmaf(p3.y, v3.z, acc.z); acc.w = fmaf(p3.y, v3.w, acc.w);
    }
#pragma unroll 1
    for (; e < r1; e++) {
        float2 p0 = __ldg(&adj[e]);
        float4 v0 = hb[(size_t)__float_as_int(p0.x) * 16 + lane];
        acc.x = fmaf(p0.y, v0.x, acc.x); acc.y = fmaf(p0.y, v0.y, acc.y);
        acc.z = fmaf(p0.y, v0.z, acc.z); acc.w = fmaf(p0.y, v0.w, acc.w);
    }

    size_t idx = (size_t)n * 16 + lane;
    if (FIRST) {
        reinterpret_cast<float4*>(out)[idx] = acc;
    } else {
        float4 t = reinterpret_cast<const float4*>(t0)[idx];
        reinterpret_cast<float4*>(out)[idx] =
            make_float4(2.0f * acc.x - t.x, 2.0f * acc.y - t.y,
                        2.0f * acc.z - t.z, 2.0f * acc.w - t.w);
    }
}

// ---------------- fused 8-way GEMM + bias + relu (optional output un-permute) ----------------
struct TPtrs { const float* p[KK]; };

__global__ void gemm8_kernel(TPtrs ts, const float* __restrict__ W,
                             const float* __restrict__ bias, float* __restrict__ out,
                             const int* __restrict__ operm) {
    __shared__ float Xs[128][DD];
    __shared__ float Ws[DD][DD];
    int tid = threadIdx.x;
    int row0 = blockIdx.x * 128;
    int tx = tid & 15, ty = tid >> 4;

    float accR[8][4];
#pragma unroll
    for (int i = 0; i < 8; i++)
#pragma unroll
        for (int c = 0; c < 4; c++) accR[i][c] = 0.0f;

    for (int k = 0; k < KK; ++k) {
        const float* X = ts.p[k];
        const float* Wp = W + (size_t)k * DD * DD;
#pragma unroll
        for (int i = 0; i < 4; i++) {
            int f4 = tid + i * 256;
            reinterpret_cast<float4*>(Ws)[f4] = reinterpret_cast<const float4*>(Wp)[f4];
        }
#pragma unroll
        for (int i = 0; i < 8; i++) {
            int f4 = tid + i * 256;
            int r = f4 >> 4, c4 = f4 & 15;
            int gr = row0 + r;
            float4 v = make_float4(0.f, 0.f, 0.f, 0.f);
            if (gr < NN) v = reinterpret_cast<const float4*>(X + (size_t)gr * DD)[c4];
            reinterpret_cast<float4*>(&Xs[r][0])[c4] = v;
        }
        __syncthreads();
#pragma unroll 8
        for (int j = 0; j < DD; j++) {
            float4 b = reinterpret_cast<float4*>(&Ws[j][0])[tx];
            float a[8];
#pragma unroll
            for (int i = 0; i < 8; i++) a[i] = Xs[ty * 8 + i][j];
#pragma unroll
            for (int i = 0; i < 8; i++) {
                accR[i][0] = fmaf(a[i], b.x, accR[i][0]);
                accR[i][1] = fmaf(a[i], b.y, accR[i][1]);
                accR[i][2] = fmaf(a[i], b.z, accR[i][2]);
                accR[i][3] = fmaf(a[i], b.w, accR[i][3]);
            }
        }
        __syncthreads();
    }

    float4 b4 = reinterpret_cast<const float4*>(bias)[tx];
#pragma unroll
    for (int i = 0; i < 8; i++) {
        int gr = row0 + ty * 8 + i;
        if (gr < NN) {
            float4 v;
            v.x = fmaxf(accR[i][0] + b4.x, 0.f);
            v.y = fmaxf(accR[i][1] + b4.y, 0.f);
            v.z = fmaxf(accR[i][2] + b4.z, 0.f);
            v.w = fmaxf(accR[i][3] + b4.w, 0.f);
            int orow = operm ? operm[gr] : gr;
            reinterpret_cast<float4*>(out + (size_t)orow * DD)[tx] = v;
        }
    }
}

// ---------------- launcher ----------------
extern "C" void kernel_launch(void* const* d_in, const int* in_sizes, int n_in,
                              void* d_out, int out_size) {
    const float* x  = (const float*)d_in[0];
    const int*   ei = (const int*)d_in[1];
    const float* ew = (const float*)d_in[2];
    const float* Wt = (const float*)d_in[3];
    const float* Bs = (const float*)d_in[4];
    const int* src = ei;
    const int* dst = ei + EE;

    float *Tbuf, *out1, *out2, *xp, *deg, *dinv;
    int *cnt, *cntp, *rowstart, *cursor, *bsum, *dbins, *dcur, *perm, *rank;
    float2* adj;
    cudaGetSymbolAddress((void**)&Tbuf, g_T);
    cudaGetSymbolAddress((void**)&out1, g_out1);
    cudaGetSymbolAddress((void**)&out2, g_out2);
    cudaGetSymbolAddress((void**)&xp, g_xp);
    cudaGetSymbolAddress((void**)&deg, g_deg);
    cudaGetSymbolAddress((void**)&dinv, g_dinv);
    cudaGetSymbolAddress((void**)&cnt, g_cnt);
    cudaGetSymbolAddress((void**)&cntp, g_cntp);
    cudaGetSymbolAddress((void**)&rowstart, g_rowstart);
    cudaGetSymbolAddress((void**)&cursor, g_cursor);
    cudaGetSymbolAddress((void**)&bsum, g_bsum);
    cudaGetSymbolAddress((void**)&dbins, g_dbins);
    cudaGetSymbolAddress((void**)&dcur, g_dcur);
    cudaGetSymbolAddress((void**)&perm, g_perm);
    cudaGetSymbolAddress((void**)&rank, g_rank);
    cudaGetSymbolAddress((void**)&adj, g_adj);

    const size_t FB = (size_t)NN * DD;
    float* TB[7];
    for (int i = 0; i < 7; i++) TB[i] = Tbuf + (size_t)i * FB;

    const int T = 256;
    const int edgeBlocks = (EE + T - 1) / T;
    const int nodeBlocks = (NN + T - 1) / T;
    const int propBlocks = (NN * 16 + T - 1) / T;
    const int gemmBlocks = (NN + 127) / 128;

    // --- setup: degrees, sort, permuted CSR, permuted x ---
    cudaMemsetAsync(deg, 0, NN * sizeof(float));
    cudaMemsetAsync(cnt, 0, NN * sizeof(int));
    cudaMemsetAsync(dbins, 0, NBINS * sizeof(int));
    deg_hist_kernel<<<edgeBlocks, T>>>(src, dst, ew, deg, cnt);
    dinv_kernel<<<nodeBlocks, T>>>(deg, dinv);
    bin_hist_kernel<<<nodeBlocks, T>>>(cnt, dbins);
    bin_scan_kernel<<<1, NBINS>>>(dbins, dcur);
    bin_scatter_kernel<<<nodeBlocks, T>>>(cnt, dcur, perm, rank);
    cntp_kernel<<<nodeBlocks, T>>>(cnt, perm, cntp);
    scan_block_kernel<<<SCAN_BLOCKS, SCAN_TPB>>>(cntp, rowstart, bsum);
    scan_sums_kernel<<<1, 128>>>(bsum);
    scan_add_kernel<<<nodeBlocks, T>>>(rowstart, bsum, cursor);
    scatter_kernel<<<edgeBlocks, T>>>(src, dst, ew, dinv, rank, cursor, adj);
    permute_x_kernel<<<propBlocks, T>>>(x, perm, xp);

    // --- layers (all buffers in permuted space) ---
    const float* hin = xp;
    float* houts[3] = {out1, out2, (float*)d_out};

    for (int l = 0; l < LL; l++) {
        const float* Wl = Wt + (size_t)l * KK * DD * DD;
        prop16_kernel<true><<<propBlocks, T>>>(hin, adj, rowstart, nullptr, TB[0]);
        for (int k = 2; k < KK; k++) {
            const float* tin = TB[k - 2];
            const float* t0 = (k == 2) ? hin : TB[k - 3];
            prop16_kernel<false><<<propBlocks, T>>>(tin, adj, rowstart, t0, TB[k - 1]);
        }
        TPtrs ts;
        ts.p[0] = hin;
        for (int k = 1; k < KK; k++) ts.p[k] = TB[k - 1];
        const int* operm = (l == LL - 1) ? perm : nullptr;
        gemm8_kernel<<<gemmBlocks, T>>>(ts, Wl, Bs + (size_t)l * DD, houts[l], operm);
        hin = houts[l];
    }
}